// round 14
// baseline (speedup 1.0000x reference)
#include <cuda_runtime.h>
#include <cuda_bf16.h>
#include <cstdint>
#include <math.h>

#define NUM_HEADS 16
#define D_HEAD 64
#define BATCH 2
#define SEQ 2048
#define BH (BATCH*NUM_HEADS)
#define SCALE_LOG2E 0.18033688011112042f   // 0.125 * log2(e)

// bf16 split planes for GEMMs
__device__ __nv_bfloat16 g_xh[4096*1024];
__device__ __nv_bfloat16 g_xl[4096*1024];
__device__ __nv_bfloat16 g_wh[4*1024*1024];
__device__ __nv_bfloat16 g_wl[4*1024*1024];
// bf16 split planes for attention (post-RoPE, written directly by qkv)
__device__ __nv_bfloat16 g_Qh[BH*SEQ*D_HEAD];
__device__ __nv_bfloat16 g_Ql[BH*SEQ*D_HEAD];
__device__ __nv_bfloat16 g_Kh[BH*SEQ*D_HEAD];
__device__ __nv_bfloat16 g_Kl[BH*SEQ*D_HEAD];
__device__ __nv_bfloat16 g_Vh[BH*SEQ*D_HEAD];
__device__ __nv_bfloat16 g_Vl[BH*SEQ*D_HEAD];
// attention output planes (written by flash, read by out_mma)
__device__ __nv_bfloat16 g_Oh[BH*SEQ*D_HEAD];
__device__ __nv_bfloat16 g_Ol[BH*SEQ*D_HEAD];
// RoPE table: [s][p] -> (cos, sin), fp32 from double
__device__ float2 g_tbl[SEQ*32];

// ---- helpers ---------------------------------------------------------------
__device__ __forceinline__ void ldsm4(unsigned r[4], unsigned addr) {
    asm volatile("ldmatrix.sync.aligned.m8n8.x4.shared.b16 {%0,%1,%2,%3}, [%4];"
                 : "=r"(r[0]), "=r"(r[1]), "=r"(r[2]), "=r"(r[3]) : "r"(addr));
}
__device__ __forceinline__ void ldsm4t(unsigned r[4], unsigned addr) {
    asm volatile("ldmatrix.sync.aligned.m8n8.x4.trans.shared.b16 {%0,%1,%2,%3}, [%4];"
                 : "=r"(r[0]), "=r"(r[1]), "=r"(r[2]), "=r"(r[3]) : "r"(addr));
}
__device__ __forceinline__ void mma16816(float c[4], const unsigned a[4], unsigned b0, unsigned b1) {
    asm volatile("mma.sync.aligned.m16n8k16.row.col.f32.bf16.bf16.f32 "
                 "{%0,%1,%2,%3},{%4,%5,%6,%7},{%8,%9},{%0,%1,%2,%3};"
                 : "+f"(c[0]), "+f"(c[1]), "+f"(c[2]), "+f"(c[3])
                 : "r"(a[0]), "r"(a[1]), "r"(a[2]), "r"(a[3]), "r"(b0), "r"(b1));
}
__device__ __forceinline__ unsigned packbf2(float a, float b) {
    __nv_bfloat162 t = __floats2bfloat162_rn(a, b);
    unsigned u;
    memcpy(&u, &t, 4);
    return u;
}
__device__ __forceinline__ unsigned packlo2(float a, float b) {
    return packbf2(a - __bfloat162float(__float2bfloat16(a)),
                   b - __bfloat162float(__float2bfloat16(b)));
}
__device__ __forceinline__ float exp2a(float x) {
    float y;
    asm("ex2.approx.f32 %0, %1;" : "=f"(y) : "f"(x));
    return y;
}

// ---------------------------------------------------------------------------
// RoPE cos/sin table (double precision, once).
// ---------------------------------------------------------------------------
__global__ void rope_table(const int* __restrict__ pos) {
    int t = blockIdx.x * 256 + threadIdx.x;
    if (t >= SEQ * 32) return;
    int p = t & 31;
    int s = t >> 5;
    double inv = exp(-(double)p * (9.210340371976184 / 32.0));
    double ang = (double)pos[s] * inv;
    double sn, cs;
    sincos(ang, &sn, &cs);
    g_tbl[t] = make_float2((float)cs, (float)sn);
}

// ---------------------------------------------------------------------------
// Split fp32 -> bf16 hi/lo planes for x and the 4 weight matrices.
// ---------------------------------------------------------------------------
__global__ void convert_split(const float* __restrict__ x,
                              const float* __restrict__ Wq, const float* __restrict__ Wk,
                              const float* __restrict__ Wv, const float* __restrict__ Wo) {
    int which = blockIdx.y;
    const float* src;
    __nv_bfloat16* dh;
    __nv_bfloat16* dl;
    int n;
    if (which == 0) {
        src = x; dh = g_xh; dl = g_xl; n = 4096 * 1024;
    } else {
        src = (which == 1) ? Wq : (which == 2) ? Wk : (which == 3) ? Wv : Wo;
        dh = g_wh + (size_t)(which - 1) * 1048576;
        dl = g_wl + (size_t)(which - 1) * 1048576;
        n = 1048576;
    }
    int i = (blockIdx.x * 256 + threadIdx.x) * 4;
    if (i >= n) return;
    float4 v = *(const float4*)(src + i);
    float f[4] = {v.x, v.y, v.z, v.w};
    __nv_bfloat16 hv[4];
    __nv_bfloat16 lv[4];
#pragma unroll
    for (int j = 0; j < 4; j++) {
        hv[j] = __float2bfloat16(f[j]);
        lv[j] = __float2bfloat16(f[j] - __bfloat162float(hv[j]));
    }
    uint2 hu, lu;
    memcpy(&hu, hv, 8);
    memcpy(&lu, lv, 8);
    *(uint2*)(dh + i) = hu;
    *(uint2*)(dl + i) = lu;
}

// ---------------------------------------------------------------------------
// mma compute for one 64-wide k chunk; 512-thread CTA (16 warps 4m x 4n),
// warp tile 32x32. Planes (stride 72): Ah +0, Al, Bh, Bl at GPL steps.
// ---------------------------------------------------------------------------
#define GPL 9216            // elems per plane (128 x 72)
#define GSTAGE (4*GPL)      // elems per stage
__device__ __forceinline__ void mma_chunk64(unsigned stb, int lane, int warp_m, int warp_n,
                                            float acc[2][4][4]) {
    unsigned ah = stb;
    unsigned al = stb + GPL * 2;
    unsigned bh = stb + GPL * 4;
    unsigned bl = stb + GPL * 6;
#pragma unroll
    for (int kk = 0; kk < 64; kk += 16) {
        int col = kk + ((lane >> 4) << 3);
        int arow = warp_m * 32 + (lane & 15);
        int brow = warp_n * 32 + (lane & 15);
        unsigned afh[2][4];
        unsigned afl[2][4];
#pragma unroll
        for (int tm = 0; tm < 2; tm++) {
            ldsm4(afh[tm], ah + (unsigned)(((arow + tm * 16) * 72 + col) * 2));
            ldsm4(afl[tm], al + (unsigned)(((arow + tm * 16) * 72 + col) * 2));
        }
        unsigned bfh[2][4];
        unsigned bfl[2][4];
#pragma unroll
        for (int tg = 0; tg < 2; tg++) {
            ldsm4(bfh[tg], bh + (unsigned)(((brow + tg * 16) * 72 + col) * 2));
            ldsm4(bfl[tg], bl + (unsigned)(((brow + tg * 16) * 72 + col) * 2));
        }
#pragma unroll
        for (int tm = 0; tm < 2; tm++) {
#pragma unroll
            for (int tn = 0; tn < 4; tn++) {
                int tg = tn >> 1;
                int idx = tn & 1;
                mma16816(acc[tm][tn], afh[tm], bfh[tg][idx], bfh[tg][idx + 2]);
                mma16816(acc[tm][tn], afh[tm], bfl[tg][idx], bfl[tg][idx + 2]);
                mma16816(acc[tm][tn], afl[tm], bfh[tg][idx], bfh[tg][idx + 2]);
            }
        }
    }
}

// ---------------------------------------------------------------------------
// QKV projection with FUSED RoPE + bf16-split epilogue (coalesced via smem).
// 512 threads, 128x128 tile, K-chunk 64, register-staged double buffer.
// ---------------------------------------------------------------------------
__global__ __launch_bounds__(512) void qkv_mma() {
    int mt = blockIdx.x;
    int which = blockIdx.y >> 3;
    int nt = blockIdx.y & 7;

    extern __shared__ __nv_bfloat16 dynsm[];
    unsigned sb = (unsigned)__cvta_generic_to_shared(dynsm);

    int tid = threadIdx.x;
    int lane = tid & 31;
    int wid = tid >> 5;
    int warp_m = wid >> 2;
    int warp_n = wid & 3;
    int lrow = tid >> 2;
    int seg = (tid & 3) * 16;

    const __nv_bfloat16* srcs[4];
    srcs[0] = g_xh + (size_t)(mt * 128 + lrow) * 1024 + seg;
    srcs[1] = g_xl + (size_t)(mt * 128 + lrow) * 1024 + seg;
    srcs[2] = g_wh + (size_t)which * 1048576 + (size_t)(nt * 128 + lrow) * 1024 + seg;
    srcs[3] = g_wl + (size_t)which * 1048576 + (size_t)(nt * 128 + lrow) * 1024 + seg;

    float acc[2][4][4] = {};
    uint4 rg[4][2];

#pragma unroll
    for (int p = 0; p < 4; p++) {
        rg[p][0] = *(const uint4*)(srcs[p]);
        rg[p][1] = *(const uint4*)(srcs[p] + 8);
    }
    {
        __nv_bfloat16* dst = dynsm + lrow * 72 + seg;
#pragma unroll
        for (int p = 0; p < 4; p++) {
            *(uint4*)(dst + p * GPL) = rg[p][0];
            *(uint4*)(dst + p * GPL + 8) = rg[p][1];
        }
    }
    __syncthreads();

    for (int c = 0; c < 16; c++) {
        int s = c & 1;
        if (c < 15) {
#pragma unroll
            for (int p = 0; p < 4; p++) {
                rg[p][0] = *(const uint4*)(srcs[p] + (c + 1) * 64);
                rg[p][1] = *(const uint4*)(srcs[p] + (c + 1) * 64 + 8);
            }
        }
        mma_chunk64(sb + (unsigned)(s * GSTAGE * 2), lane, warp_m, warp_n, acc);
        if (c < 15) {
            __nv_bfloat16* dst = dynsm + (s ^ 1) * GSTAGE + lrow * 72 + seg;
#pragma unroll
            for (int p = 0; p < 4; p++) {
                *(uint4*)(dst + p * GPL) = rg[p][0];
                *(uint4*)(dst + p * GPL + 8) = rg[p][1];
            }
        }
        __syncthreads();
    }

    // ---- fused RoPE + split epilogue ----
    unsigned* W = (unsigned*)dynsm;
    int b = mt >> 4;
    int s0 = (mt & 15) * 128;
    int headr = warp_n >> 1;
#pragma unroll
    for (int tm = 0; tm < 2; tm++) {
#pragma unroll
        for (int tn = 0; tn < 4; tn++) {
#pragma unroll
            for (int half = 0; half < 2; half++) {
                int mrow = warp_m * 32 + tm * 16 + (lane >> 2) + half * 8;
                int d = (warp_n & 1) * 32 + tn * 8 + (lane & 3) * 2;
                float a0 = acc[tm][tn][half * 2];
                float a1 = acc[tm][tn][half * 2 + 1];
                if (which < 2) {
                    float2 cs = g_tbl[(s0 + mrow) * 32 + (d >> 1)];
                    float r0 = a0 * cs.x - a1 * cs.y;
                    float r1 = a0 * cs.y + a1 * cs.x;
                    if (which == 0) { r0 *= SCALE_LOG2E; r1 *= SCALE_LOG2E; }
                    a0 = r0; a1 = r1;
                }
                int col = d >> 1;
                W[(headr * 2 + 0) * 4608 + mrow * 36 + col] = packbf2(a0, a1);
                W[(headr * 2 + 1) * 4608 + mrow * 36 + col] = packlo2(a0, a1);
            }
        }
    }
    __syncthreads();

    __nv_bfloat16* gh = (which == 0) ? g_Qh : (which == 1) ? g_Kh : g_Vh;
    __nv_bfloat16* gl = (which == 0) ? g_Ql : (which == 1) ? g_Kl : g_Vl;
#pragma unroll
    for (int i = 0; i < 8; i++) {
        int li = tid * 8 + i;
        int region = li >> 10;
        int rem = li & 1023;
        int row = rem >> 3;
        int q4 = rem & 7;
        uint4 v = *(uint4*)&W[region * 4608 + row * 36 + q4 * 4];
        int head = nt * 2 + (region >> 1);
        unsigned* dst = (unsigned*)((region & 1) ? gl : gh)
                        + ((size_t)(b * 16 + head) * SEQ + s0 + row) * 32 + q4 * 4;
        *(uint4*)dst = v;
    }
}

// ---------------------------------------------------------------------------
// Output projection: A staged as plain copies of g_Oh/g_Ol planes.
// ---------------------------------------------------------------------------
__global__ __launch_bounds__(512) void out_mma(float* __restrict__ out) {
    int mt = blockIdx.x;
    int nt = blockIdx.y;

    extern __shared__ __nv_bfloat16 dynsm2[];
    unsigned sb = (unsigned)__cvta_generic_to_shared(dynsm2);

    int tid = threadIdx.x;
    int lane = tid & 31;
    int wid = tid >> 5;
    int warp_m = wid >> 2;
    int warp_n = wid & 3;
    int lrow = tid >> 2;
    int seg = (tid & 3) * 16;

    int m = mt * 128 + lrow;
    int b = m >> 11;
    int sq0 = m & 2047;
    const unsigned* pOh = (const unsigned*)g_Oh + ((size_t)(b * 16) * SEQ + sq0) * 32 + (tid & 3) * 8;
    const unsigned* pOl = (const unsigned*)g_Ol + ((size_t)(b * 16) * SEQ + sq0) * 32 + (tid & 3) * 8;
    const __nv_bfloat16* sBh = g_wh + (size_t)3 * 1048576 + (size_t)(nt * 128 + lrow) * 1024 + seg;
    const __nv_bfloat16* sBl = g_wl + (size_t)3 * 1048576 + (size_t)(nt * 128 + lrow) * 1024 + seg;

    float acc[2][4][4] = {};
    uint4 rg[4][2];

    rg[0][0] = *(const uint4*)(pOh);
    rg[0][1] = *(const uint4*)(pOh + 4);
    rg[1][0] = *(const uint4*)(pOl);
    rg[1][1] = *(const uint4*)(pOl + 4);
    rg[2][0] = *(const uint4*)(sBh);
    rg[2][1] = *(const uint4*)(sBh + 8);
    rg[3][0] = *(const uint4*)(sBl);
    rg[3][1] = *(const uint4*)(sBl + 8);
    {
        __nv_bfloat16* dst = dynsm2 + lrow * 72 + seg;
#pragma unroll
        for (int p = 0; p < 4; p++) {
            *(uint4*)(dst + p * GPL) = rg[p][0];
            *(uint4*)(dst + p * GPL + 8) = rg[p][1];
        }
    }
    __syncthreads();

    for (int c = 0; c < 16; c++) {
        int s = c & 1;
        if (c < 15) {
            size_t ho = (size_t)(c + 1) * SEQ * 32;
            rg[0][0] = *(const uint4*)(pOh + ho);
            rg[0][1] = *(const uint4*)(pOh + ho + 4);
            rg[1][0] = *(const uint4*)(pOl + ho);
            rg[1][1] = *(const uint4*)(pOl + ho + 4);
            rg[2][0] = *(const uint4*)(sBh + (c + 1) * 64);
            rg[2][1] = *(const uint4*)(sBh + (c + 1) * 64 + 8);
            rg[3][0] = *(const uint4*)(sBl + (c + 1) * 64);
            rg[3][1] = *(const uint4*)(sBl + (c + 1) * 64 + 8);
        }
        mma_chunk64(sb + (unsigned)(s * GSTAGE * 2), lane, warp_m, warp_n, acc);
        if (c < 15) {
            __nv_bfloat16* dst = dynsm2 + (s ^ 1) * GSTAGE + lrow * 72 + seg;
#pragma unroll
            for (int p = 0; p < 4; p++) {
                *(uint4*)(dst + p * GPL) = rg[p][0];
                *(uint4*)(dst + p * GPL + 8) = rg[p][1];
            }
        }
        __syncthreads();
    }

#pragma unroll
    for (int tm = 0; tm < 2; tm++) {
#pragma unroll
        for (int tn = 0; tn < 4; tn++) {
            int m0 = mt * 128 + warp_m * 32 + tm * 16 + (lane >> 2);
            int e = nt * 128 + warp_n * 32 + tn * 8 + (lane & 3) * 2;
#pragma unroll
            for (int half = 0; half < 2; half++) {
                int mr = m0 + half * 8;
                float2 v = make_float2(acc[tm][tn][half * 2], acc[tm][tn][half * 2 + 1]);
                *(float2*)(out + (size_t)mr * 1024 + e) = v;
            }
        }
    }
}

// ---------------------------------------------------------------------------
// Causal flash attention: 2 CTAs/SM. Single-buffered K/V (direct LDG->STS),
// Q fragments re-ldsm'd per dc step, forced <=128 regs.
// smem: Q planes 36864B + KV 36864B = 73728B.
// ---------------------------------------------------------------------------
#define FPL (64*72)
__global__ __launch_bounds__(256, 2) void flash_mma() {
    int qt = gridDim.x - 1 - blockIdx.x;
    int bh = blockIdx.y;
    size_t base = (size_t)bh * SEQ * 64;

    extern __shared__ __nv_bfloat16 smem[];
    __nv_bfloat16* Qhs = smem;                 // [128][72]
    __nv_bfloat16* Qls = Qhs + 128 * 72;       // [128][72]
    __nv_bfloat16* KV  = Qls + 128 * 72;       // {Kh,Kl,Vh,Vl}[64][72]
    unsigned qhsB = (unsigned)__cvta_generic_to_shared(Qhs);
    unsigned qlsB = (unsigned)__cvta_generic_to_shared(Qls);
    unsigned kvB  = (unsigned)__cvta_generic_to_shared(KV);

    int tid = threadIdx.x;
    int lane = tid & 31;
    int w = tid >> 5;

    int ldrow = tid >> 2;
    int ldcol = (tid & 3) * 16;

    // Stage Q tile (128x64 bf16, hi+lo)
    {
        int row = tid >> 1;
        int col = (tid & 1) * 32;
        const uint4* sh = (const uint4*)(g_Qh + base + (size_t)(qt * 128 + row) * 64 + col);
        const uint4* sl = (const uint4*)(g_Ql + base + (size_t)(qt * 128 + row) * 64 + col);
        uint4* dh = (uint4*)(Qhs + row * 72 + col);
        uint4* dl = (uint4*)(Qls + row * 72 + col);
#pragma unroll
        for (int i = 0; i < 4; i++) { dh[i] = sh[i]; dl[i] = sl[i]; }
    }

    float accO[8][4] = {};
    float mrow[2] = {-INFINITY, -INFINITY};
    float lrow[2] = {0.f, 0.f};

    unsigned khsB = kvB;
    unsigned klsB = kvB + FPL * 2;
    unsigned vhsB = kvB + FPL * 4;
    unsigned vlsB = kvB + FPL * 6;

    int kmax = 2 * qt + 1;
    for (int kt = 0; kt <= kmax; kt++) {
        __syncthreads();   // prior iter done reading KV (Q staged before 1st)
        {
            size_t g = base + (size_t)(kt * 64 + ldrow) * 64 + ldcol;
            __nv_bfloat16* dst = KV + ldrow * 72 + ldcol;
            *(uint4*)(dst)               = *(const uint4*)(g_Kh + g);
            *(uint4*)(dst + 8)           = *(const uint4*)(g_Kh + g + 8);
            *(uint4*)(dst + FPL)         = *(const uint4*)(g_Kl + g);
            *(uint4*)(dst + FPL + 8)     = *(const uint4*)(g_Kl + g + 8);
            *(uint4*)(dst + FPL * 2)     = *(const uint4*)(g_Vh + g);
            *(uint4*)(dst + FPL * 2 + 8) = *(const uint4*)(g_Vh + g + 8);
            *(uint4*)(dst + FPL * 3)     = *(const uint4*)(g_Vl + g);
            *(uint4*)(dst + FPL * 3 + 8) = *(const uint4*)(g_Vl + g + 8);
        }
        __syncthreads();

        // S = Q K^T (split-3); Q fragments re-loaded per dc
        float s[8][4] = {};
#pragma unroll
        for (int dc = 0; dc < 4; dc++) {
            unsigned qhf[4], qlf[4];
            {
                unsigned off = (unsigned)(((w * 16 + (lane & 15)) * 72 + dc * 16 + 8 * (lane >> 4)) * 2);
                ldsm4(qhf, qhsB + off);
                ldsm4(qlf, qlsB + off);
            }
            unsigned kh[4][4], kl[4][4];
#pragma unroll
            for (int jt2 = 0; jt2 < 4; jt2++) {
                unsigned off = (unsigned)(((jt2 * 16 + (lane & 15)) * 72 + dc * 16 + 8 * (lane >> 4)) * 2);
                ldsm4(kh[jt2], khsB + off);
                ldsm4(kl[jt2], klsB + off);
            }
#pragma unroll
            for (int jt = 0; jt < 8; jt++) {
                int jt2 = jt >> 1;
                int idx = jt & 1;
                mma16816(s[jt], qhf, kh[jt2][idx], kh[jt2][idx + 2]);
                mma16816(s[jt], qhf, kl[jt2][idx], kl[jt2][idx + 2]);
                mma16816(s[jt], qlf, kh[jt2][idx], kh[jt2][idx + 2]);
            }
        }

        if (kt >= 2 * qt) {
            int i0 = qt * 128 + w * 16 + (lane >> 2);
            int jb = kt * 64 + (lane & 3) * 2;
#pragma unroll
            for (int jt = 0; jt < 8; jt++) {
                int j = jb + jt * 8;
                if (j > i0) s[jt][0] = -1e30f;
                if (j + 1 > i0) s[jt][1] = -1e30f;
                if (j > i0 + 8) s[jt][2] = -1e30f;
                if (j + 1 > i0 + 8) s[jt][3] = -1e30f;
            }
        }

        float mx0 = -1e30f, mx1 = -1e30f;
#pragma unroll
        for (int jt = 0; jt < 8; jt++) {
            mx0 = fmaxf(mx0, fmaxf(s[jt][0], s[jt][1]));
            mx1 = fmaxf(mx1, fmaxf(s[jt][2], s[jt][3]));
        }
        mx0 = fmaxf(mx0, __shfl_xor_sync(0xffffffffu, mx0, 1));
        mx0 = fmaxf(mx0, __shfl_xor_sync(0xffffffffu, mx0, 2));
        mx1 = fmaxf(mx1, __shfl_xor_sync(0xffffffffu, mx1, 1));
        mx1 = fmaxf(mx1, __shfl_xor_sync(0xffffffffu, mx1, 2));
        float mn0 = fmaxf(mrow[0], mx0);
        float mn1 = fmaxf(mrow[1], mx1);
        float a0 = exp2a(mrow[0] - mn0);
        float a1 = exp2a(mrow[1] - mn1);
        mrow[0] = mn0;
        mrow[1] = mn1;
        float sum0 = 0.f, sum1 = 0.f;
#pragma unroll
        for (int jt = 0; jt < 8; jt++) {
            s[jt][0] = exp2a(s[jt][0] - mn0);
            s[jt][1] = exp2a(s[jt][1] - mn0);
            s[jt][2] = exp2a(s[jt][2] - mn1);
            s[jt][3] = exp2a(s[jt][3] - mn1);
            sum0 += s[jt][0] + s[jt][1];
            sum1 += s[jt][2] + s[jt][3];
        }
        sum0 += __shfl_xor_sync(0xffffffffu, sum0, 1);
        sum0 += __shfl_xor_sync(0xffffffffu, sum0, 2);
        sum1 += __shfl_xor_sync(0xffffffffu, sum1, 1);
        sum1 += __shfl_xor_sync(0xffffffffu, sum1, 2);
        lrow[0] = lrow[0] * a0 + sum0;
        lrow[1] = lrow[1] * a1 + sum1;
#pragma unroll
        for (int dt = 0; dt < 8; dt++) {
            accO[dt][0] *= a0;
            accO[dt][1] *= a0;
            accO[dt][2] *= a1;
            accO[dt][3] *= a1;
        }

#pragma unroll
        for (int kc = 0; kc < 4; kc++) {
            unsigned phh[4], pll[4];
            {
                float p00 = s[2 * kc][0], p01 = s[2 * kc][1], p02 = s[2 * kc][2], p03 = s[2 * kc][3];
                float p10 = s[2 * kc + 1][0], p11 = s[2 * kc + 1][1], p12 = s[2 * kc + 1][2], p13 = s[2 * kc + 1][3];
                phh[0] = packbf2(p00, p01);
                phh[1] = packbf2(p02, p03);
                phh[2] = packbf2(p10, p11);
                phh[3] = packbf2(p12, p13);
                pll[0] = packlo2(p00, p01);
                pll[1] = packlo2(p02, p03);
                pll[2] = packlo2(p10, p11);
                pll[3] = packlo2(p12, p13);
            }
            unsigned vh[4][4], vl[4][4];
#pragma unroll
            for (int dt2 = 0; dt2 < 4; dt2++) {
                unsigned off = (unsigned)(((kc * 16 + (lane & 15)) * 72 + dt2 * 16 + 8 * (lane >> 4)) * 2);
                ldsm4t(vh[dt2], vhsB + off);
                ldsm4t(vl[dt2], vlsB + off);
            }
#pragma unroll
            for (int dt = 0; dt < 8; dt++) {
                int dt2 = dt >> 1;
                int o = (dt & 1) * 2;
                mma16816(accO[dt], phh, vh[dt2][o], vh[dt2][o + 1]);
                mma16816(accO[dt], pll, vh[dt2][o], vh[dt2][o + 1]);
                mma16816(accO[dt], phh, vl[dt2][o], vl[dt2][o + 1]);
            }
        }
    }

    // ---- epilogue: split O to bf16 planes, coalesced via smem ----
    __syncthreads();
    float inv0 = 1.f / lrow[0];
    float inv1 = 1.f / lrow[1];
    unsigned* W = (unsigned*)smem;
#pragma unroll
    for (int dt = 0; dt < 8; dt++) {
        int col = dt * 4 + (lane & 3);
        {
            float a0 = accO[dt][0] * inv0;
            float a1 = accO[dt][1] * inv0;
            int row = w * 16 + (lane >> 2);
            W[row * 36 + col] = packbf2(a0, a1);
            W[4608 + row * 36 + col] = packlo2(a0, a1);
        }
        {
            float a0 = accO[dt][2] * inv1;
            float a1 = accO[dt][3] * inv1;
            int row = w * 16 + (lane >> 2) + 8;
            W[row * 36 + col] = packbf2(a0, a1);
            W[4608 + row * 36 + col] = packlo2(a0, a1);
        }
    }
    __syncthreads();
#pragma unroll
    for (int i = 0; i < 8; i++) {
        int li = tid * 8 + i;
        int region = li >> 10;
        int rem = li & 1023;
        int row = rem >> 3;
        int q4 = rem & 7;
        uint4 v = *(uint4*)&W[region * 4608 + row * 36 + q4 * 4];
        unsigned* dst = (unsigned*)(region ? g_Ol : g_Oh)
                        + ((size_t)bh * SEQ + qt * 128 + row) * 32 + q4 * 4;
        *(uint4*)dst = v;
    }
}

// ---------------------------------------------------------------------------
extern "C" void kernel_launch(void* const* d_in, const int* in_sizes, int n_in,
                              void* d_out, int out_size) {
    const float* x  = (const float*)d_in[0];
    const int*   tp = (const int*)d_in[1];
    const float* Wq = (const float*)d_in[2];
    const float* Wk = (const float*)d_in[3];
    const float* Wv = (const float*)d_in[4];
    const float* Wo = (const float*)d_in[5];
    float* out = (float*)d_out;

    rope_table<<<(SEQ * 32 + 255) / 256, 256>>>(tp);
    convert_split<<<dim3(4096, 5), 256>>>(x, Wq, Wk, Wv, Wo);

    cudaFuncSetAttribute(qkv_mma, cudaFuncAttributeMaxDynamicSharedMemorySize, 2 * GSTAGE * 2);
    qkv_mma<<<dim3(32, 24), 512, 2 * GSTAGE * 2>>>();

    int flash_smem = (2 * 128 * 72 + 4 * FPL) * 2;   // 73728 B
    cudaFuncSetAttribute(flash_mma, cudaFuncAttributeMaxDynamicSharedMemorySize, flash_smem);
    flash_mma<<<dim3(16, 32), 256, flash_smem>>>();

    cudaFuncSetAttribute(out_mma, cudaFuncAttributeMaxDynamicSharedMemorySize, 2 * GSTAGE * 2);
    out_mma<<<dim3(32, 8), 512, 2 * GSTAGE * 2>>>(out);
}

// round 15
// speedup vs baseline: 1.0317x; 1.0317x over previous
#include <cuda_runtime.h>
#include <cuda_bf16.h>
#include <cstdint>
#include <math.h>

#define NUM_HEADS 16
#define D_HEAD 64
#define BATCH 2
#define SEQ 2048
#define BH (BATCH*NUM_HEADS)
#define SCALE_LOG2E 0.18033688011112042f   // 0.125 * log2(e)

// bf16 split planes for GEMMs
__device__ __nv_bfloat16 g_xh[4096*1024];
__device__ __nv_bfloat16 g_xl[4096*1024];
__device__ __nv_bfloat16 g_wh[4*1024*1024];
__device__ __nv_bfloat16 g_wl[4*1024*1024];
// bf16 split planes for attention (post-RoPE, written directly by qkv)
__device__ __nv_bfloat16 g_Qh[BH*SEQ*D_HEAD];
__device__ __nv_bfloat16 g_Ql[BH*SEQ*D_HEAD];
__device__ __nv_bfloat16 g_Kh[BH*SEQ*D_HEAD];
__device__ __nv_bfloat16 g_Kl[BH*SEQ*D_HEAD];
__device__ __nv_bfloat16 g_Vh[BH*SEQ*D_HEAD];
__device__ __nv_bfloat16 g_Vl[BH*SEQ*D_HEAD];
// attention output planes (written by flash, read by out_mma)
__device__ __nv_bfloat16 g_Oh[BH*SEQ*D_HEAD];
__device__ __nv_bfloat16 g_Ol[BH*SEQ*D_HEAD];
// RoPE table: [s][p] -> (cos, sin), fp32 from double
__device__ float2 g_tbl[SEQ*32];

// ---- helpers ---------------------------------------------------------------
__device__ __forceinline__ void ldsm4(unsigned r[4], unsigned addr) {
    asm volatile("ldmatrix.sync.aligned.m8n8.x4.shared.b16 {%0,%1,%2,%3}, [%4];"
                 : "=r"(r[0]), "=r"(r[1]), "=r"(r[2]), "=r"(r[3]) : "r"(addr));
}
__device__ __forceinline__ void ldsm4t(unsigned r[4], unsigned addr) {
    asm volatile("ldmatrix.sync.aligned.m8n8.x4.trans.shared.b16 {%0,%1,%2,%3}, [%4];"
                 : "=r"(r[0]), "=r"(r[1]), "=r"(r[2]), "=r"(r[3]) : "r"(addr));
}
__device__ __forceinline__ void mma16816(float c[4], const unsigned a[4], unsigned b0, unsigned b1) {
    asm volatile("mma.sync.aligned.m16n8k16.row.col.f32.bf16.bf16.f32 "
                 "{%0,%1,%2,%3},{%4,%5,%6,%7},{%8,%9},{%0,%1,%2,%3};"
                 : "+f"(c[0]), "+f"(c[1]), "+f"(c[2]), "+f"(c[3])
                 : "r"(a[0]), "r"(a[1]), "r"(a[2]), "r"(a[3]), "r"(b0), "r"(b1));
}
__device__ __forceinline__ unsigned packbf2(float a, float b) {
    __nv_bfloat162 t = __floats2bfloat162_rn(a, b);
    unsigned u;
    memcpy(&u, &t, 4);
    return u;
}
__device__ __forceinline__ unsigned packlo2(float a, float b) {
    return packbf2(a - __bfloat162float(__float2bfloat16(a)),
                   b - __bfloat162float(__float2bfloat16(b)));
}
__device__ __forceinline__ float exp2a(float x) {
    float y;
    asm("ex2.approx.f32 %0, %1;" : "=f"(y) : "f"(x));
    return y;
}

// ---------------------------------------------------------------------------
// RoPE cos/sin table (double precision, once).
// ---------------------------------------------------------------------------
__global__ void rope_table(const int* __restrict__ pos) {
    int t = blockIdx.x * 256 + threadIdx.x;
    if (t >= SEQ * 32) return;
    int p = t & 31;
    int s = t >> 5;
    double inv = exp(-(double)p * (9.210340371976184 / 32.0));
    double ang = (double)pos[s] * inv;
    double sn, cs;
    sincos(ang, &sn, &cs);
    g_tbl[t] = make_float2((float)cs, (float)sn);
}

// ---------------------------------------------------------------------------
// Split fp32 -> bf16 hi/lo planes for x and the 4 weight matrices.
// ---------------------------------------------------------------------------
__global__ void convert_split(const float* __restrict__ x,
                              const float* __restrict__ Wq, const float* __restrict__ Wk,
                              const float* __restrict__ Wv, const float* __restrict__ Wo) {
    int which = blockIdx.y;
    const float* src;
    __nv_bfloat16* dh;
    __nv_bfloat16* dl;
    int n;
    if (which == 0) {
        src = x; dh = g_xh; dl = g_xl; n = 4096 * 1024;
    } else {
        src = (which == 1) ? Wq : (which == 2) ? Wk : (which == 3) ? Wv : Wo;
        dh = g_wh + (size_t)(which - 1) * 1048576;
        dl = g_wl + (size_t)(which - 1) * 1048576;
        n = 1048576;
    }
    int i = (blockIdx.x * 256 + threadIdx.x) * 4;
    if (i >= n) return;
    float4 v = *(const float4*)(src + i);
    float f[4] = {v.x, v.y, v.z, v.w};
    __nv_bfloat16 hv[4];
    __nv_bfloat16 lv[4];
#pragma unroll
    for (int j = 0; j < 4; j++) {
        hv[j] = __float2bfloat16(f[j]);
        lv[j] = __float2bfloat16(f[j] - __bfloat162float(hv[j]));
    }
    uint2 hu, lu;
    memcpy(&hu, hv, 8);
    memcpy(&lu, lv, 8);
    *(uint2*)(dh + i) = hu;
    *(uint2*)(dl + i) = lu;
}

// ---------------------------------------------------------------------------
// mma compute for one 64-wide k chunk; 512-thread CTA (16 warps 4m x 4n),
// warp tile 32x32. Planes (stride 72): Ah +0, Al, Bh, Bl at GPL steps.
// ---------------------------------------------------------------------------
#define GPL 9216            // elems per plane (128 x 72)
#define GSTAGE (4*GPL)      // elems per stage
__device__ __forceinline__ void mma_chunk64(unsigned stb, int lane, int warp_m, int warp_n,
                                            float acc[2][4][4]) {
    unsigned ah = stb;
    unsigned al = stb + GPL * 2;
    unsigned bh = stb + GPL * 4;
    unsigned bl = stb + GPL * 6;
#pragma unroll
    for (int kk = 0; kk < 64; kk += 16) {
        int col = kk + ((lane >> 4) << 3);
        int arow = warp_m * 32 + (lane & 15);
        int brow = warp_n * 32 + (lane & 15);
        unsigned afh[2][4];
        unsigned afl[2][4];
#pragma unroll
        for (int tm = 0; tm < 2; tm++) {
            ldsm4(afh[tm], ah + (unsigned)(((arow + tm * 16) * 72 + col) * 2));
            ldsm4(afl[tm], al + (unsigned)(((arow + tm * 16) * 72 + col) * 2));
        }
        unsigned bfh[2][4];
        unsigned bfl[2][4];
#pragma unroll
        for (int tg = 0; tg < 2; tg++) {
            ldsm4(bfh[tg], bh + (unsigned)(((brow + tg * 16) * 72 + col) * 2));
            ldsm4(bfl[tg], bl + (unsigned)(((brow + tg * 16) * 72 + col) * 2));
        }
#pragma unroll
        for (int tm = 0; tm < 2; tm++) {
#pragma unroll
            for (int tn = 0; tn < 4; tn++) {
                int tg = tn >> 1;
                int idx = tn & 1;
                mma16816(acc[tm][tn], afh[tm], bfh[tg][idx], bfh[tg][idx + 2]);
                mma16816(acc[tm][tn], afh[tm], bfl[tg][idx], bfl[tg][idx + 2]);
                mma16816(acc[tm][tn], afl[tm], bfh[tg][idx], bfh[tg][idx + 2]);
            }
        }
    }
}

// ---------------------------------------------------------------------------
// QKV projection, PERSISTENT grid: 152 CTAs loop over 768 tiles.
// Per tile: 128x128, K-chunk 64, register-staged double buffer,
// fused RoPE + bf16-split coalesced epilogue.
// ---------------------------------------------------------------------------
__global__ __launch_bounds__(512) void qkv_mma() {
    extern __shared__ __nv_bfloat16 dynsm[];
    unsigned sb = (unsigned)__cvta_generic_to_shared(dynsm);

    int tid = threadIdx.x;
    int lane = tid & 31;
    int wid = tid >> 5;
    int warp_m = wid >> 2;
    int warp_n = wid & 3;
    int lrow = tid >> 2;
    int seg = (tid & 3) * 16;

    for (int t = blockIdx.x; t < 768; t += gridDim.x) {
        int mt = t & 31;
        int y = t >> 5;
        int which = y >> 3;
        int nt = y & 7;

        __syncthreads();   // smem scratch (W) fully read before restaging

        const __nv_bfloat16* srcs[4];
        srcs[0] = g_xh + (size_t)(mt * 128 + lrow) * 1024 + seg;
        srcs[1] = g_xl + (size_t)(mt * 128 + lrow) * 1024 + seg;
        srcs[2] = g_wh + (size_t)which * 1048576 + (size_t)(nt * 128 + lrow) * 1024 + seg;
        srcs[3] = g_wl + (size_t)which * 1048576 + (size_t)(nt * 128 + lrow) * 1024 + seg;

        float acc[2][4][4] = {};
        uint4 rg[4][2];

#pragma unroll
        for (int p = 0; p < 4; p++) {
            rg[p][0] = *(const uint4*)(srcs[p]);
            rg[p][1] = *(const uint4*)(srcs[p] + 8);
        }
        {
            __nv_bfloat16* dst = dynsm + lrow * 72 + seg;
#pragma unroll
            for (int p = 0; p < 4; p++) {
                *(uint4*)(dst + p * GPL) = rg[p][0];
                *(uint4*)(dst + p * GPL + 8) = rg[p][1];
            }
        }
        __syncthreads();

        for (int c = 0; c < 16; c++) {
            int s = c & 1;
            if (c < 15) {
#pragma unroll
                for (int p = 0; p < 4; p++) {
                    rg[p][0] = *(const uint4*)(srcs[p] + (c + 1) * 64);
                    rg[p][1] = *(const uint4*)(srcs[p] + (c + 1) * 64 + 8);
                }
            }
            mma_chunk64(sb + (unsigned)(s * GSTAGE * 2), lane, warp_m, warp_n, acc);
            if (c < 15) {
                __nv_bfloat16* dst = dynsm + (s ^ 1) * GSTAGE + lrow * 72 + seg;
#pragma unroll
                for (int p = 0; p < 4; p++) {
                    *(uint4*)(dst + p * GPL) = rg[p][0];
                    *(uint4*)(dst + p * GPL + 8) = rg[p][1];
                }
            }
            __syncthreads();
        }

        // ---- fused RoPE + split epilogue ----
        unsigned* W = (unsigned*)dynsm;
        int b = mt >> 4;
        int s0 = (mt & 15) * 128;
        int headr = warp_n >> 1;
#pragma unroll
        for (int tm = 0; tm < 2; tm++) {
#pragma unroll
            for (int tn = 0; tn < 4; tn++) {
#pragma unroll
                for (int half = 0; half < 2; half++) {
                    int mrow = warp_m * 32 + tm * 16 + (lane >> 2) + half * 8;
                    int d = (warp_n & 1) * 32 + tn * 8 + (lane & 3) * 2;
                    float a0 = acc[tm][tn][half * 2];
                    float a1 = acc[tm][tn][half * 2 + 1];
                    if (which < 2) {
                        float2 cs = g_tbl[(s0 + mrow) * 32 + (d >> 1)];
                        float r0 = a0 * cs.x - a1 * cs.y;
                        float r1 = a0 * cs.y + a1 * cs.x;
                        if (which == 0) { r0 *= SCALE_LOG2E; r1 *= SCALE_LOG2E; }
                        a0 = r0; a1 = r1;
                    }
                    int col = d >> 1;
                    W[(headr * 2 + 0) * 4608 + mrow * 36 + col] = packbf2(a0, a1);
                    W[(headr * 2 + 1) * 4608 + mrow * 36 + col] = packlo2(a0, a1);
                }
            }
        }
        __syncthreads();

        __nv_bfloat16* gh = (which == 0) ? g_Qh : (which == 1) ? g_Kh : g_Vh;
        __nv_bfloat16* gl = (which == 0) ? g_Ql : (which == 1) ? g_Kl : g_Vl;
#pragma unroll
        for (int i = 0; i < 8; i++) {
            int li = tid * 8 + i;
            int region = li >> 10;
            int rem = li & 1023;
            int row = rem >> 3;
            int q4 = rem & 7;
            uint4 v = *(uint4*)&W[region * 4608 + row * 36 + q4 * 4];
            int head = nt * 2 + (region >> 1);
            unsigned* dst = (unsigned*)((region & 1) ? gl : gh)
                            + ((size_t)(b * 16 + head) * SEQ + s0 + row) * 32 + q4 * 4;
            *(uint4*)dst = v;
        }
    }
}

// ---------------------------------------------------------------------------
// Output projection: A staged as plain copies of g_Oh/g_Ol planes.
// ---------------------------------------------------------------------------
__global__ __launch_bounds__(512) void out_mma(float* __restrict__ out) {
    int mt = blockIdx.x;
    int nt = blockIdx.y;

    extern __shared__ __nv_bfloat16 dynsm2[];
    unsigned sb = (unsigned)__cvta_generic_to_shared(dynsm2);

    int tid = threadIdx.x;
    int lane = tid & 31;
    int wid = tid >> 5;
    int warp_m = wid >> 2;
    int warp_n = wid & 3;
    int lrow = tid >> 2;
    int seg = (tid & 3) * 16;

    int m = mt * 128 + lrow;
    int b = m >> 11;
    int sq0 = m & 2047;
    const unsigned* pOh = (const unsigned*)g_Oh + ((size_t)(b * 16) * SEQ + sq0) * 32 + (tid & 3) * 8;
    const unsigned* pOl = (const unsigned*)g_Ol + ((size_t)(b * 16) * SEQ + sq0) * 32 + (tid & 3) * 8;
    const __nv_bfloat16* sBh = g_wh + (size_t)3 * 1048576 + (size_t)(nt * 128 + lrow) * 1024 + seg;
    const __nv_bfloat16* sBl = g_wl + (size_t)3 * 1048576 + (size_t)(nt * 128 + lrow) * 1024 + seg;

    float acc[2][4][4] = {};
    uint4 rg[4][2];

    rg[0][0] = *(const uint4*)(pOh);
    rg[0][1] = *(const uint4*)(pOh + 4);
    rg[1][0] = *(const uint4*)(pOl);
    rg[1][1] = *(const uint4*)(pOl + 4);
    rg[2][0] = *(const uint4*)(sBh);
    rg[2][1] = *(const uint4*)(sBh + 8);
    rg[3][0] = *(const uint4*)(sBl);
    rg[3][1] = *(const uint4*)(sBl + 8);
    {
        __nv_bfloat16* dst = dynsm2 + lrow * 72 + seg;
#pragma unroll
        for (int p = 0; p < 4; p++) {
            *(uint4*)(dst + p * GPL) = rg[p][0];
            *(uint4*)(dst + p * GPL + 8) = rg[p][1];
        }
    }
    __syncthreads();

    for (int c = 0; c < 16; c++) {
        int s = c & 1;
        if (c < 15) {
            size_t ho = (size_t)(c + 1) * SEQ * 32;
            rg[0][0] = *(const uint4*)(pOh + ho);
            rg[0][1] = *(const uint4*)(pOh + ho + 4);
            rg[1][0] = *(const uint4*)(pOl + ho);
            rg[1][1] = *(const uint4*)(pOl + ho + 4);
            rg[2][0] = *(const uint4*)(sBh + (c + 1) * 64);
            rg[2][1] = *(const uint4*)(sBh + (c + 1) * 64 + 8);
            rg[3][0] = *(const uint4*)(sBl + (c + 1) * 64);
            rg[3][1] = *(const uint4*)(sBl + (c + 1) * 64 + 8);
        }
        mma_chunk64(sb + (unsigned)(s * GSTAGE * 2), lane, warp_m, warp_n, acc);
        if (c < 15) {
            __nv_bfloat16* dst = dynsm2 + (s ^ 1) * GSTAGE + lrow * 72 + seg;
#pragma unroll
            for (int p = 0; p < 4; p++) {
                *(uint4*)(dst + p * GPL) = rg[p][0];
                *(uint4*)(dst + p * GPL + 8) = rg[p][1];
            }
        }
        __syncthreads();
    }

#pragma unroll
    for (int tm = 0; tm < 2; tm++) {
#pragma unroll
        for (int tn = 0; tn < 4; tn++) {
            int m0 = mt * 128 + warp_m * 32 + tm * 16 + (lane >> 2);
            int e = nt * 128 + warp_n * 32 + tn * 8 + (lane & 3) * 2;
#pragma unroll
            for (int half = 0; half < 2; half++) {
                int mr = m0 + half * 8;
                float2 v = make_float2(acc[tm][tn][half * 2], acc[tm][tn][half * 2 + 1]);
                *(float2*)(out + (size_t)mr * 1024 + e) = v;
            }
        }
    }
}

// ---------------------------------------------------------------------------
// Causal flash attention (R13-proven): register-staged double-buffered K/V,
// Q fragments register-resident, bf16-plane epilogue.
// ---------------------------------------------------------------------------
#define FPL (64*72)
#define FST (4*FPL)
__global__ __launch_bounds__(256) void flash_mma() {
    int qt = gridDim.x - 1 - blockIdx.x;
    int bh = blockIdx.y;
    size_t base = (size_t)bh * SEQ * 64;

    extern __shared__ __nv_bfloat16 smem[];
    __nv_bfloat16* Qhs = smem;
    __nv_bfloat16* Qls = Qhs + 128 * 72;
    __nv_bfloat16* KV  = Qls + 128 * 72;
    unsigned qhsB = (unsigned)__cvta_generic_to_shared(Qhs);
    unsigned qlsB = (unsigned)__cvta_generic_to_shared(Qls);
    unsigned kvB  = (unsigned)__cvta_generic_to_shared(KV);

    int tid = threadIdx.x;
    int lane = tid & 31;
    int w = tid >> 5;

    int ldrow = tid >> 2;
    int ldcol = (tid & 3) * 16;

    const __nv_bfloat16* kvsrc[4] = {g_Kh, g_Kl, g_Vh, g_Vl};

    uint4 rkv[4][2];
    {
        size_t g = base + (size_t)ldrow * 64 + ldcol;
#pragma unroll
        for (int p = 0; p < 4; p++) {
            rkv[p][0] = *(const uint4*)(kvsrc[p] + g);
            rkv[p][1] = *(const uint4*)(kvsrc[p] + g + 8);
        }
    }

    {
        int row = tid >> 1;
        int col = (tid & 1) * 32;
        const uint4* sh = (const uint4*)(g_Qh + base + (size_t)(qt * 128 + row) * 64 + col);
        const uint4* sl = (const uint4*)(g_Ql + base + (size_t)(qt * 128 + row) * 64 + col);
        uint4* dh = (uint4*)(Qhs + row * 72 + col);
        uint4* dl = (uint4*)(Qls + row * 72 + col);
#pragma unroll
        for (int i = 0; i < 4; i++) { dh[i] = sh[i]; dl[i] = sl[i]; }
    }
    {
        __nv_bfloat16* dst = KV + ldrow * 72 + ldcol;
#pragma unroll
        for (int p = 0; p < 4; p++) {
            *(uint4*)(dst + p * FPL) = rkv[p][0];
            *(uint4*)(dst + p * FPL + 8) = rkv[p][1];
        }
    }
    __syncthreads();

    unsigned qh[4][4], ql[4][4];
#pragma unroll
    for (int dc = 0; dc < 4; dc++) {
        unsigned off = (unsigned)(((w * 16 + (lane & 15)) * 72 + dc * 16 + 8 * (lane >> 4)) * 2);
        ldsm4(qh[dc], qhsB + off);
        ldsm4(ql[dc], qlsB + off);
    }

    float accO[8][4] = {};
    float mrow[2] = {-INFINITY, -INFINITY};
    float lrow[2] = {0.f, 0.f};

    int kmax = 2 * qt + 1;
    for (int kt = 0; kt <= kmax; kt++) {
        int st = kt & 1;
        if (kt < kmax) {
            size_t g = base + (size_t)((kt + 1) * 64 + ldrow) * 64 + ldcol;
#pragma unroll
            for (int p = 0; p < 4; p++) {
                rkv[p][0] = *(const uint4*)(kvsrc[p] + g);
                rkv[p][1] = *(const uint4*)(kvsrc[p] + g + 8);
            }
        }

        unsigned khsB = kvB + (unsigned)(st * FST * 2);
        unsigned klsB = khsB + FPL * 2;
        unsigned vhsB = khsB + FPL * 4;
        unsigned vlsB = khsB + FPL * 6;

        float s[8][4] = {};
#pragma unroll
        for (int dc = 0; dc < 4; dc++) {
            unsigned kh[4][4], kl[4][4];
#pragma unroll
            for (int jt2 = 0; jt2 < 4; jt2++) {
                unsigned off = (unsigned)(((jt2 * 16 + (lane & 15)) * 72 + dc * 16 + 8 * (lane >> 4)) * 2);
                ldsm4(kh[jt2], khsB + off);
                ldsm4(kl[jt2], klsB + off);
            }
#pragma unroll
            for (int jt = 0; jt < 8; jt++) {
                int jt2 = jt >> 1;
                int idx = jt & 1;
                mma16816(s[jt], qh[dc], kh[jt2][idx], kh[jt2][idx + 2]);
                mma16816(s[jt], qh[dc], kl[jt2][idx], kl[jt2][idx + 2]);
                mma16816(s[jt], ql[dc], kh[jt2][idx], kh[jt2][idx + 2]);
            }
        }

        if (kt >= 2 * qt) {
            int i0 = qt * 128 + w * 16 + (lane >> 2);
            int jb = kt * 64 + (lane & 3) * 2;
#pragma unroll
            for (int jt = 0; jt < 8; jt++) {
                int j = jb + jt * 8;
                if (j > i0) s[jt][0] = -1e30f;
                if (j + 1 > i0) s[jt][1] = -1e30f;
                if (j > i0 + 8) s[jt][2] = -1e30f;
                if (j + 1 > i0 + 8) s[jt][3] = -1e30f;
            }
        }

        float mx0 = -1e30f, mx1 = -1e30f;
#pragma unroll
        for (int jt = 0; jt < 8; jt++) {
            mx0 = fmaxf(mx0, fmaxf(s[jt][0], s[jt][1]));
            mx1 = fmaxf(mx1, fmaxf(s[jt][2], s[jt][3]));
        }
        mx0 = fmaxf(mx0, __shfl_xor_sync(0xffffffffu, mx0, 1));
        mx0 = fmaxf(mx0, __shfl_xor_sync(0xffffffffu, mx0, 2));
        mx1 = fmaxf(mx1, __shfl_xor_sync(0xffffffffu, mx1, 1));
        mx1 = fmaxf(mx1, __shfl_xor_sync(0xffffffffu, mx1, 2));
        float mn0 = fmaxf(mrow[0], mx0);
        float mn1 = fmaxf(mrow[1], mx1);
        float a0 = exp2a(mrow[0] - mn0);
        float a1 = exp2a(mrow[1] - mn1);
        mrow[0] = mn0;
        mrow[1] = mn1;
        float sum0 = 0.f, sum1 = 0.f;
#pragma unroll
        for (int jt = 0; jt < 8; jt++) {
            s[jt][0] = exp2a(s[jt][0] - mn0);
            s[jt][1] = exp2a(s[jt][1] - mn0);
            s[jt][2] = exp2a(s[jt][2] - mn1);
            s[jt][3] = exp2a(s[jt][3] - mn1);
            sum0 += s[jt][0] + s[jt][1];
            sum1 += s[jt][2] + s[jt][3];
        }
        sum0 += __shfl_xor_sync(0xffffffffu, sum0, 1);
        sum0 += __shfl_xor_sync(0xffffffffu, sum0, 2);
        sum1 += __shfl_xor_sync(0xffffffffu, sum1, 1);
        sum1 += __shfl_xor_sync(0xffffffffu, sum1, 2);
        lrow[0] = lrow[0] * a0 + sum0;
        lrow[1] = lrow[1] * a1 + sum1;
#pragma unroll
        for (int dt = 0; dt < 8; dt++) {
            accO[dt][0] *= a0;
            accO[dt][1] *= a0;
            accO[dt][2] *= a1;
            accO[dt][3] *= a1;
        }

#pragma unroll
        for (int kc = 0; kc < 4; kc++) {
            unsigned phh[4], pll[4];
            {
                float p00 = s[2 * kc][0], p01 = s[2 * kc][1], p02 = s[2 * kc][2], p03 = s[2 * kc][3];
                float p10 = s[2 * kc + 1][0], p11 = s[2 * kc + 1][1], p12 = s[2 * kc + 1][2], p13 = s[2 * kc + 1][3];
                phh[0] = packbf2(p00, p01);
                phh[1] = packbf2(p02, p03);
                phh[2] = packbf2(p10, p11);
                phh[3] = packbf2(p12, p13);
                pll[0] = packlo2(p00, p01);
                pll[1] = packlo2(p02, p03);
                pll[2] = packlo2(p10, p11);
                pll[3] = packlo2(p12, p13);
            }
            unsigned vh[4][4], vl[4][4];
#pragma unroll
            for (int dt2 = 0; dt2 < 4; dt2++) {
                unsigned off = (unsigned)(((kc * 16 + (lane & 15)) * 72 + dt2 * 16 + 8 * (lane >> 4)) * 2);
                ldsm4t(vh[dt2], vhsB + off);
                ldsm4t(vl[dt2], vlsB + off);
            }
#pragma unroll
            for (int dt = 0; dt < 8; dt++) {
                int dt2 = dt >> 1;
                int o = (dt & 1) * 2;
                mma16816(accO[dt], phh, vh[dt2][o], vh[dt2][o + 1]);
                mma16816(accO[dt], pll, vh[dt2][o], vh[dt2][o + 1]);
                mma16816(accO[dt], phh, vl[dt2][o], vl[dt2][o + 1]);
            }
        }

        if (kt < kmax) {
            __nv_bfloat16* dst = KV + (st ^ 1) * FST + ldrow * 72 + ldcol;
#pragma unroll
            for (int p = 0; p < 4; p++) {
                *(uint4*)(dst + p * FPL) = rkv[p][0];
                *(uint4*)(dst + p * FPL + 8) = rkv[p][1];
            }
        }
        __syncthreads();
    }

    // ---- epilogue: split O to bf16 planes, coalesced via smem ----
    float inv0 = 1.f / lrow[0];
    float inv1 = 1.f / lrow[1];
    unsigned* W = (unsigned*)smem;
#pragma unroll
    for (int dt = 0; dt < 8; dt++) {
        int col = dt * 4 + (lane & 3);
        {
            float a0 = accO[dt][0] * inv0;
            float a1 = accO[dt][1] * inv0;
            int row = w * 16 + (lane >> 2);
            W[row * 36 + col] = packbf2(a0, a1);
            W[4608 + row * 36 + col] = packlo2(a0, a1);
        }
        {
            float a0 = accO[dt][2] * inv1;
            float a1 = accO[dt][3] * inv1;
            int row = w * 16 + (lane >> 2) + 8;
            W[row * 36 + col] = packbf2(a0, a1);
            W[4608 + row * 36 + col] = packlo2(a0, a1);
        }
    }
    __syncthreads();
#pragma unroll
    for (int i = 0; i < 8; i++) {
        int li = tid * 8 + i;
        int region = li >> 10;
        int rem = li & 1023;
        int row = rem >> 3;
        int q4 = rem & 7;
        uint4 v = *(uint4*)&W[region * 4608 + row * 36 + q4 * 4];
        unsigned* dst = (unsigned*)(region ? g_Ol : g_Oh)
                        + ((size_t)bh * SEQ + qt * 128 + row) * 32 + q4 * 4;
        *(uint4*)dst = v;
    }
}

// ---------------------------------------------------------------------------
extern "C" void kernel_launch(void* const* d_in, const int* in_sizes, int n_in,
                              void* d_out, int out_size) {
    const float* x  = (const float*)d_in[0];
    const int*   tp = (const int*)d_in[1];
    const float* Wq = (const float*)d_in[2];
    const float* Wk = (const float*)d_in[3];
    const float* Wv = (const float*)d_in[4];
    const float* Wo = (const float*)d_in[5];
    float* out = (float*)d_out;

    rope_table<<<(SEQ * 32 + 255) / 256, 256>>>(tp);
    convert_split<<<dim3(4096, 5), 256>>>(x, Wq, Wk, Wv, Wo);

    cudaFuncSetAttribute(qkv_mma, cudaFuncAttributeMaxDynamicSharedMemorySize, 2 * GSTAGE * 2);
    qkv_mma<<<152, 512, 2 * GSTAGE * 2>>>();

    int flash_smem = (2 * 128 * 72 + 2 * FST) * 2;
    cudaFuncSetAttribute(flash_mma, cudaFuncAttributeMaxDynamicSharedMemorySize, flash_smem);
    flash_mma<<<dim3(16, 32), 256, flash_smem>>>();

    cudaFuncSetAttribute(out_mma, cudaFuncAttributeMaxDynamicSharedMemorySize, 2 * GSTAGE * 2);
    out_mma<<<dim3(32, 8), 512, 2 * GSTAGE * 2>>>(out);
}